// round 2
// baseline (speedup 1.0000x reference)
#include <cuda_runtime.h>
#include <math.h>

#define D   128
#define NN  50000
#define EE  1600000
#define RR  8
#define LL  3
#define NB  (RR*NN)
#define SCAN_BLK 391   /* ceil(NB/1024) */

// ---------------- scratch (static device arrays; no allocation) ----------------
__device__ float g_hA[NN*D];     // current h
__device__ float g_hB[NN*D];     // conv accumulator
__device__ float g_S[NN*D];      // per-relation mean buffer
__device__ float g_invc[NB];     // 1/max(cnt,1)
__device__ int   g_cnt[NB];      // per (r,dst) edge count
__device__ int   g_boff[NB+1];   // bucket offsets (exclusive scan)
__device__ int   g_bcur[NB];     // bucket cursors for partition
__device__ int   g_srcs[EE];     // src ids sorted by bucket
__device__ int   g_part[512];    // block partial sums for scan

// ---------------- setup kernels ----------------
__global__ void k_zero_cnt() {
    int i = blockIdx.x*blockDim.x + threadIdx.x;
    if (i < NB) g_cnt[i] = 0;
}

__global__ void k_count(const int* __restrict__ et, const int* __restrict__ dst) {
    int e = blockIdx.x*blockDim.x + threadIdx.x;
    if (e < EE) atomicAdd(&g_cnt[et[e]*NN + dst[e]], 1);
}

__global__ void k_scan1() {
    int t = threadIdx.x;
    int base = blockIdx.x*1024 + t*4;
    int s = 0;
    #pragma unroll
    for (int j = 0; j < 4; j++) { int i = base + j; if (i < NB) s += g_cnt[i]; }
    #pragma unroll
    for (int o = 16; o > 0; o >>= 1) s += __shfl_xor_sync(0xffffffffu, s, o);
    __shared__ int ws[8];
    if ((t & 31) == 0) ws[t >> 5] = s;
    __syncthreads();
    if (t == 0) {
        int tot = 0;
        #pragma unroll
        for (int w = 0; w < 8; w++) tot += ws[w];
        g_part[blockIdx.x] = tot;
    }
}

__global__ void k_scan2() {
    __shared__ int sm[512];
    int t = threadIdx.x;
    int v = (t < SCAN_BLK) ? g_part[t] : 0;
    sm[t] = v; __syncthreads();
    for (int o = 1; o < 512; o <<= 1) {
        int y = (t >= o) ? sm[t-o] : 0;
        __syncthreads();
        sm[t] += y;
        __syncthreads();
    }
    if (t < SCAN_BLK) g_part[t] = sm[t] - v;  // exclusive
    if (t == 0) g_boff[NB] = EE;
}

__global__ void k_scan3() {
    int t = threadIdx.x;
    int base = blockIdx.x*1024 + t*4;
    int c[4]; int tsum = 0;
    #pragma unroll
    for (int j = 0; j < 4; j++) { int i = base + j; c[j] = (i < NB) ? g_cnt[i] : 0; tsum += c[j]; }
    int x = tsum;
    int lane = t & 31, wid = t >> 5;
    #pragma unroll
    for (int o = 1; o < 32; o <<= 1) { int y = __shfl_up_sync(0xffffffffu, x, o); if (lane >= o) x += y; }
    __shared__ int wincl[8];
    if (lane == 31) wincl[wid] = x;
    __syncthreads();
    int pre = 0;
    for (int w = 0; w < wid; w++) pre += wincl[w];
    int off = g_part[blockIdx.x] + pre + x - tsum;
    #pragma unroll
    for (int j = 0; j < 4; j++) {
        int i = base + j;
        if (i < NB) { g_boff[i] = off; g_bcur[i] = off; off += c[j]; }
    }
}

__global__ void k_inv() {
    int i = blockIdx.x*blockDim.x + threadIdx.x;
    if (i < NB) g_invc[i] = 1.0f / fmaxf((float)g_cnt[i], 1.0f);
}

__global__ void k_partition(const int* __restrict__ src, const int* __restrict__ dst,
                            const int* __restrict__ et) {
    int e = blockIdx.x*blockDim.x + threadIdx.x;
    if (e < EE) {
        int b = et[e]*NN + dst[e];
        int p = atomicAdd(&g_bcur[b], 1);
        g_srcs[p] = src[e];
    }
}

__global__ void k_gather(const int* __restrict__ x, const float* __restrict__ emb) {
    int i = blockIdx.x*blockDim.x + threadIdx.x;   // float4 index over NN*32
    if (i < NN*32) {
        int row = i >> 5, c = i & 31;
        ((float4*)g_hA)[i] = ((const float4*)emb)[(long long)x[row]*32 + c];
    }
}

// ---------------- per-relation segmented mean (no atomics) ----------------
__global__ void k_agg(const float* __restrict__ h, int r) {
    int w = (blockIdx.x*blockDim.x + threadIdx.x) >> 5;
    if (w >= NN) return;
    int lane = threadIdx.x & 31;
    int b = r*NN + w;
    int beg = g_boff[b], end = g_boff[b+1];
    float4 acc = make_float4(0.f, 0.f, 0.f, 0.f);
    for (int e = beg; e < end; e++) {
        int s = g_srcs[e];
        float4 v = *(const float4*)&h[s*D + lane*4];
        acc.x += v.x; acc.y += v.y; acc.z += v.z; acc.w += v.w;
    }
    float sc = g_invc[b];
    acc.x *= sc; acc.y *= sc; acc.z *= sc; acc.w *= sc;
    *(float4*)&g_S[w*D + lane*4] = acc;
}

// ---------------- fp32 SGEMM: C[M,128] (+)= A[M,128] @ W[128,128] (+bias) -------
template<bool ACCUM>
__global__ void __launch_bounds__(256, 2) k_gemm(
    const float* __restrict__ A, const float* __restrict__ W,
    const float* __restrict__ bias, float* __restrict__ C, int M)
{
    __shared__ float As[2][16][128];
    __shared__ float Bs[2][16][128];
    int tid = threadIdx.x;
    int row0 = blockIdx.x * 128;
    int tx = tid & 15, ty = tid >> 4;

    float c[8][8];
    #pragma unroll
    for (int i = 0; i < 8; i++)
        #pragma unroll
        for (int j = 0; j < 8; j++) c[i][j] = 0.f;

    float4 ra[2], rb[2];
    int am[2], ak[2], bk[2], bn[2];
    #pragma unroll
    for (int l = 0; l < 2; l++) {
        int idx = tid + l*256;
        am[l] = idx >> 2;          ak[l] = (idx & 3) << 2;
        bk[l] = idx >> 5;          bn[l] = (idx & 31) << 2;
    }

    auto fetch = [&](int kk) {
        #pragma unroll
        for (int l = 0; l < 2; l++) {
            int gm = row0 + am[l];
            ra[l] = make_float4(0.f, 0.f, 0.f, 0.f);
            if (gm < M) ra[l] = *(const float4*)&A[gm*D + kk + ak[l]];
            rb[l] = *(const float4*)&W[(kk + bk[l])*D + bn[l]];
        }
    };
    auto store = [&](int buf) {
        #pragma unroll
        for (int l = 0; l < 2; l++) {
            As[buf][ak[l]+0][am[l]] = ra[l].x;
            As[buf][ak[l]+1][am[l]] = ra[l].y;
            As[buf][ak[l]+2][am[l]] = ra[l].z;
            As[buf][ak[l]+3][am[l]] = ra[l].w;
            *(float4*)&Bs[buf][bk[l]][bn[l]] = rb[l];
        }
    };

    fetch(0);
    store(0);
    __syncthreads();

    #pragma unroll
    for (int s = 0; s < 8; s++) {
        int buf = s & 1;
        if (s < 7) fetch((s+1)*16);
        #pragma unroll
        for (int k = 0; k < 16; k++) {
            float a[8], b[8];
            *(float4*)&a[0] = *(const float4*)&As[buf][k][ty*8];
            *(float4*)&a[4] = *(const float4*)&As[buf][k][ty*8+4];
            *(float4*)&b[0] = *(const float4*)&Bs[buf][k][tx*8];
            *(float4*)&b[4] = *(const float4*)&Bs[buf][k][tx*8+4];
            #pragma unroll
            for (int i = 0; i < 8; i++)
                #pragma unroll
                for (int j = 0; j < 8; j++)
                    c[i][j] = fmaf(a[i], b[j], c[i][j]);
        }
        if (s < 7) store(buf ^ 1);
        __syncthreads();
    }

    #pragma unroll
    for (int i = 0; i < 8; i++) {
        int gm = row0 + ty*8 + i;
        if (gm >= M) continue;
        #pragma unroll
        for (int j = 0; j < 8; j += 4) {
            int gn = tx*8 + j;
            float4 v = make_float4(c[i][j], c[i][j+1], c[i][j+2], c[i][j+3]);
            if (ACCUM) {
                float4 o = *(const float4*)&C[gm*D + gn];
                v.x += o.x; v.y += o.y; v.z += o.z; v.w += o.w;
            } else {
                v.x += bias[gn]; v.y += bias[gn+1]; v.z += bias[gn+2]; v.w += bias[gn+3];
            }
            *(float4*)&C[gm*D + gn] = v;
        }
    }
}

// ---------------- fused LayerNorm + ReLU + residual ----------------
__global__ void k_ln(const float* __restrict__ hnew, const float* __restrict__ gamma,
                     const float* __restrict__ beta, const float* __restrict__ hprev,
                     float* __restrict__ out)
{
    int row = blockIdx.x;
    int t = threadIdx.x;              // 128 threads
    float v = hnew[row*D + t];
    __shared__ float red[8];
    float s = v;
    #pragma unroll
    for (int o = 16; o > 0; o >>= 1) s += __shfl_xor_sync(0xffffffffu, s, o);
    if ((t & 31) == 0) red[t >> 5] = s;
    __syncthreads();
    float mu = (red[0] + red[1] + red[2] + red[3]) * (1.0f/D);
    float d = v - mu;
    float q = d*d;
    #pragma unroll
    for (int o = 16; o > 0; o >>= 1) q += __shfl_xor_sync(0xffffffffu, q, o);
    if ((t & 31) == 0) red[4 + (t >> 5)] = q;
    __syncthreads();
    float var = (red[4] + red[5] + red[6] + red[7]) * (1.0f/D);
    float y = d * rsqrtf(var + 1e-5f) * gamma[t] + beta[t];
    y = fmaxf(y, 0.0f);
    if (hprev) y += hprev[row*D + t];
    out[row*D + t] = y;
}

// ---------------- launcher ----------------
extern "C" void kernel_launch(void* const* d_in, const int* in_sizes, int n_in,
                              void* d_out, int out_size)
{
    const int*   x      = (const int*)d_in[0];
    const int*   ei     = (const int*)d_in[1];
    const int*   et     = (const int*)d_in[2];
    const float* emb    = (const float*)d_in[3];
    const float* w_rel  = (const float*)d_in[4];
    const float* w_root = (const float*)d_in[5];
    const float* bias   = (const float*)d_in[6];
    const float* gamma  = (const float*)d_in[7];
    const float* beta   = (const float*)d_in[8];
    float* out = (float*)d_out;
    const int* src = ei;
    const int* dst = ei + EE;

    float *hA, *hB, *S;
    cudaGetSymbolAddress((void**)&hA, g_hA);
    cudaGetSymbolAddress((void**)&hB, g_hB);
    cudaGetSymbolAddress((void**)&S,  g_S);

    const int T = 256;
    // edge bucketing (once per call; valid for all layers)
    k_zero_cnt<<<(NB+T-1)/T, T>>>();
    k_count<<<(EE+T-1)/T, T>>>(et, dst);
    k_scan1<<<SCAN_BLK, 256>>>();
    k_scan2<<<1, 512>>>();
    k_scan3<<<SCAN_BLK, 256>>>();
    k_inv<<<(NB+T-1)/T, T>>>();
    k_partition<<<(EE+T-1)/T, T>>>(src, dst, et);
    k_gather<<<(NN*32+T-1)/T, T>>>(x, emb);

    const int GB = (NN + 127) / 128;  // 391 GEMM blocks
    for (int l = 0; l < LL; l++) {
        // root transform + bias -> hB
        k_gemm<false><<<GB, 256>>>(hA, w_root + (size_t)l*D*D, bias + l*D, hB, NN);
        for (int r = 0; r < RR; r++) {
            k_agg<<<(NN*32+T-1)/T, T>>>(hA, r);
            k_gemm<true><<<GB, 256>>>(S, w_rel + ((size_t)(l*RR + r))*D*D, nullptr, hB, NN);
        }
        float* lnout = (l == LL-1) ? out : hA;
        k_ln<<<NN, 128>>>(hB, gamma + l*D, beta + l*D, (l > 0) ? hA : nullptr, lnout);
    }
}

// round 5
// speedup vs baseline: 1.8598x; 1.8598x over previous
#include <cuda_runtime.h>
#include <math.h>
#include <stdint.h>

#define D    128
#define NN   50000
#define EE   1600000
#define RR   8
#define LL   3
#define NB   (RR*NN)
#define SCAN_BLK 391   /* ceil(NB/1024) */
#define KTOT 1152      /* 8*128 relation means + 128 root */
#define NCH  36        /* KTOT / 32 */
#define ASTRIDE 36     /* 32 + 4 pad floats */
#define STAGEB (128*ASTRIDE*4)          /* bytes per operand per stage: 18432 */
#define GDSM  (2*2*STAGEB)              /* 2 stages x (A+B) = 73728 */

// ---------------- scratch (static device arrays; no allocation) ----------------
__device__ float g_hA[NN*D];              // current h (fp32)
__device__ float g_hB[NN*D];              // conv output
__device__ float g_Acat[(size_t)NN*KTOT]; // concatenated GEMM A operand (fp32)
__device__ float g_Bt[LL*D*KTOT];         // transposed weights [l][f][k] (fp32)
__device__ float g_invc[NB];
__device__ int   g_cnt[NB];
__device__ int   g_boff[NB+1];
__device__ int   g_bcur[NB];
__device__ int   g_srcs[EE];
__device__ int   g_part[512];

// ---------------- helpers ----------------
__device__ __forceinline__ uint32_t su32(const void* p) {
    uint32_t a;
    asm("{.reg .u64 t; cvta.to.shared.u64 t, %1; cvt.u32.u64 %0, t;}" : "=r"(a) : "l"(p));
    return a;
}
__device__ __forceinline__ float rtf32(float x) {
    float r; asm("cvt.rna.tf32.f32 %0, %1;" : "=f"(r) : "f"(x)); return r;
}
__device__ __forceinline__ void split32(float v, uint32_t& hi, uint32_t& lo) {
    float h = rtf32(v);
    float l = rtf32(v - h);
    hi = __float_as_uint(h);
    lo = __float_as_uint(l);
}
__device__ __forceinline__ void cp16(uint32_t s, const float* g) {
    asm volatile("cp.async.cg.shared.global [%0], [%1], 16;" :: "r"(s), "l"(g));
}
__device__ __forceinline__ void mma_tf32(float* c, const uint32_t* a, const uint32_t* b) {
    asm volatile(
        "mma.sync.aligned.m16n8k8.row.col.f32.tf32.tf32.f32 "
        "{%0,%1,%2,%3},{%4,%5,%6,%7},{%8,%9},{%0,%1,%2,%3};"
        : "+f"(c[0]), "+f"(c[1]), "+f"(c[2]), "+f"(c[3])
        : "r"(a[0]), "r"(a[1]), "r"(a[2]), "r"(a[3]), "r"(b[0]), "r"(b[1]));
}

// ---------------- setup kernels ----------------
__global__ void k_zero_cnt() {
    int i = blockIdx.x*blockDim.x + threadIdx.x;
    if (i < NB) g_cnt[i] = 0;
}
__global__ void k_count(const int* __restrict__ et, const int* __restrict__ dst) {
    int e = blockIdx.x*blockDim.x + threadIdx.x;
    if (e < EE) atomicAdd(&g_cnt[et[e]*NN + dst[e]], 1);
}
__global__ void k_scan1() {
    int t = threadIdx.x;
    int base = blockIdx.x*1024 + t*4;
    int s = 0;
    #pragma unroll
    for (int j = 0; j < 4; j++) { int i = base + j; if (i < NB) s += g_cnt[i]; }
    #pragma unroll
    for (int o = 16; o > 0; o >>= 1) s += __shfl_xor_sync(0xffffffffu, s, o);
    __shared__ int ws[8];
    if ((t & 31) == 0) ws[t >> 5] = s;
    __syncthreads();
    if (t == 0) {
        int tot = 0;
        #pragma unroll
        for (int w = 0; w < 8; w++) tot += ws[w];
        g_part[blockIdx.x] = tot;
    }
}
__global__ void k_scan2() {
    __shared__ int sm[512];
    int t = threadIdx.x;
    int v = (t < SCAN_BLK) ? g_part[t] : 0;
    sm[t] = v; __syncthreads();
    for (int o = 1; o < 512; o <<= 1) {
        int y = (t >= o) ? sm[t-o] : 0;
        __syncthreads();
        sm[t] += y;
        __syncthreads();
    }
    if (t < SCAN_BLK) g_part[t] = sm[t] - v;
    if (t == 0) g_boff[NB] = EE;
}
__global__ void k_scan3() {
    int t = threadIdx.x;
    int base = blockIdx.x*1024 + t*4;
    int c[4]; int tsum = 0;
    #pragma unroll
    for (int j = 0; j < 4; j++) { int i = base + j; c[j] = (i < NB) ? g_cnt[i] : 0; tsum += c[j]; }
    int x = tsum;
    int lane = t & 31, wid = t >> 5;
    #pragma unroll
    for (int o = 1; o < 32; o <<= 1) { int y = __shfl_up_sync(0xffffffffu, x, o); if (lane >= o) x += y; }
    __shared__ int wincl[8];
    if (lane == 31) wincl[wid] = x;
    __syncthreads();
    int pre = 0;
    for (int w = 0; w < wid; w++) pre += wincl[w];
    int off = g_part[blockIdx.x] + pre + x - tsum;
    #pragma unroll
    for (int j = 0; j < 4; j++) {
        int i = base + j;
        if (i < NB) { g_boff[i] = off; g_bcur[i] = off; off += c[j]; }
    }
}
__global__ void k_inv() {
    int i = blockIdx.x*blockDim.x + threadIdx.x;
    if (i < NB) g_invc[i] = 1.0f / fmaxf((float)g_cnt[i], 1.0f);
}
__global__ void k_partition(const int* __restrict__ src, const int* __restrict__ dst,
                            const int* __restrict__ et) {
    int e = blockIdx.x*blockDim.x + threadIdx.x;
    if (e < EE) {
        int b = et[e]*NN + dst[e];
        int p = atomicAdd(&g_bcur[b], 1);
        g_srcs[p] = src[e];
    }
}
__global__ void k_gather(const int* __restrict__ x, const float* __restrict__ emb) {
    int i = blockIdx.x*blockDim.x + threadIdx.x;
    if (i < NN*32) {
        int row = i >> 5, c = i & 31;
        ((float4*)g_hA)[i] = ((const float4*)emb)[(long long)x[row]*32 + c];
    }
}

// ---------------- weight transpose: Bt[l][f][k] (fp32) ----
__global__ void k_prep_bt(const float* __restrict__ w_rel, const float* __restrict__ w_root) {
    int i = blockIdx.x*blockDim.x + threadIdx.x;
    if (i >= LL*D*KTOT) return;
    int l = i / (D*KTOT);
    int rem = i - l*D*KTOT;
    int f = rem / KTOT;
    int k = rem - f*KTOT;
    float v;
    if (k < RR*D) {
        int r = k >> 7, dd = k & 127;
        v = w_rel[(((size_t)(l*RR + r))*D + dd)*D + f];
    } else {
        int dd = k - RR*D;
        v = w_root[((size_t)l*D + dd)*D + f];
    }
    g_Bt[i] = v;
}

// ---------------- fused aggregation: 8 relation means + root copy -> A_cat ----
__global__ void k_agg_all(const float* __restrict__ h, float* __restrict__ Acat) {
    int n = blockIdx.x;
    int wid = threadIdx.x >> 5, lane = threadIdx.x & 31;
    int b = wid*NN + n;
    int beg = g_boff[b], end = g_boff[b+1];
    float4 acc = make_float4(0.f, 0.f, 0.f, 0.f);
    for (int e = beg; e < end; e++) {
        int s = g_srcs[e];
        float4 v = *(const float4*)&h[s*D + lane*4];
        acc.x += v.x; acc.y += v.y; acc.z += v.z; acc.w += v.w;
    }
    float sc = g_invc[b];
    acc.x *= sc; acc.y *= sc; acc.z *= sc; acc.w *= sc;
    *(float4*)&Acat[(size_t)n*KTOT + wid*D + lane*4] = acc;
    if (threadIdx.x < 32) {
        float4 v = *(const float4*)&h[n*D + threadIdx.x*4];
        *(float4*)&Acat[(size_t)n*KTOT + RR*D + threadIdx.x*4] = v;
    }
}

// ---------------- 3xTF32 mma.sync GEMM: C[M,128] = A[M,1152] @ B^T[128,1152] + bias
// 256 threads, 8 warps (2m x 4n), warp tile 64x32, double-buffered cp.async.
__global__ void __launch_bounds__(256, 1) k_gemm_mma(
    const float* __restrict__ A, const float* __restrict__ B,
    const float* __restrict__ bias, float* __restrict__ C)
{
    extern __shared__ float smf[];
    int tid = threadIdx.x, wid = tid >> 5, lane = tid & 31;
    int row0 = blockIdx.x * 128;
    int warp_m = (wid >> 2) * 64;       // 0 or 64
    int warp_n = (wid & 3) * 32;        // 0,32,64,96
    int grp = lane >> 2, qid = lane & 3;

    uint32_t sbase = su32(smf);

    float c[4][4][4];
    #pragma unroll
    for (int i = 0; i < 4; i++)
        #pragma unroll
        for (int j = 0; j < 4; j++)
            #pragma unroll
            for (int q = 0; q < 4; q++) c[i][j][q] = 0.f;

    // load one K=32 chunk into stage s
    auto load_chunk = [&](int it, int s) {
        const int kb = it * 32;
        uint32_t sA = sbase + (uint32_t)s * (2*STAGEB);
        uint32_t sB = sA + STAGEB;
        #pragma unroll
        for (int j = 0; j < 4; j++) {
            int slot = tid + j*256;           // 0..1023
            int row = slot >> 3, c16 = slot & 7;
            uint32_t off = (uint32_t)(row*ASTRIDE*4 + c16*16);
            int gm = row0 + row; if (gm >= NN) gm = NN - 1;   // clamp (never stored)
            cp16(sA + off, A + (size_t)gm*KTOT + kb + c16*4);
            cp16(sB + off, B + (size_t)row*KTOT + kb + c16*4);
        }
        asm volatile("cp.async.commit_group;" ::: "memory");
    };

    load_chunk(0, 0);
    load_chunk(1, 1);

    for (int it = 0; it < NCH; it++) {
        int s = it & 1;
        asm volatile("cp.async.wait_group 1;" ::: "memory");
        __syncthreads();
        const float* As = smf + s*(2*STAGEB/4);
        const float* Bs = As + (STAGEB/4);
        #pragma unroll
        for (int kk = 0; kk < 32; kk += 8) {
            uint32_t ah[4][4], al[4][4], bh[4][2], bl[4][2];
            #pragma unroll
            for (int i = 0; i < 4; i++) {
                int r = warp_m + i*16 + grp;
                split32(As[r*ASTRIDE + kk + qid],         ah[i][0], al[i][0]);
                split32(As[(r+8)*ASTRIDE + kk + qid],     ah[i][1], al[i][1]);
                split32(As[r*ASTRIDE + kk + qid + 4],     ah[i][2], al[i][2]);
                split32(As[(r+8)*ASTRIDE + kk + qid + 4], ah[i][3], al[i][3]);
            }
            #pragma unroll
            for (int j = 0; j < 4; j++) {
                int nrow = warp_n + j*8 + grp;
                split32(Bs[nrow*ASTRIDE + kk + qid],     bh[j][0], bl[j][0]);
                split32(Bs[nrow*ASTRIDE + kk + qid + 4], bh[j][1], bl[j][1]);
            }
            #pragma unroll
            for (int i = 0; i < 4; i++)
                #pragma unroll
                for (int j = 0; j < 4; j++) {
                    mma_tf32(c[i][j], al[i], bh[j]);
                    mma_tf32(c[i][j], ah[i], bl[j]);
                    mma_tf32(c[i][j], ah[i], bh[j]);
                }
        }
        __syncthreads();
        if (it + 2 < NCH) load_chunk(it + 2, s);
    }

    // epilogue
    #pragma unroll
    for (int i = 0; i < 4; i++) {
        #pragma unroll
        for (int j = 0; j < 4; j++) {
            int col = warp_n + j*8 + qid*2;
            float bx = bias[col], by = bias[col+1];
            int gm0 = row0 + warp_m + i*16 + grp;
            if (gm0 < NN) {
                float2 v = make_float2(c[i][j][0] + bx, c[i][j][1] + by);
                *(float2*)&C[(size_t)gm0*D + col] = v;
            }
            int gm1 = gm0 + 8;
            if (gm1 < NN) {
                float2 v = make_float2(c[i][j][2] + bx, c[i][j][3] + by);
                *(float2*)&C[(size_t)gm1*D + col] = v;
            }
        }
    }
}

// ---------------- fused LayerNorm + ReLU + residual ----------------
__global__ void k_ln(const float* __restrict__ hnew, const float* __restrict__ gamma,
                     const float* __restrict__ beta, const float* __restrict__ hprev,
                     float* __restrict__ out)
{
    int row = blockIdx.x;
    int t = threadIdx.x;
    float v = hnew[row*D + t];
    __shared__ float red[8];
    float s = v;
    #pragma unroll
    for (int o = 16; o > 0; o >>= 1) s += __shfl_xor_sync(0xffffffffu, s, o);
    if ((t & 31) == 0) red[t >> 5] = s;
    __syncthreads();
    float mu = (red[0] + red[1] + red[2] + red[3]) * (1.0f/D);
    float d = v - mu;
    float q = d*d;
    #pragma unroll
    for (int o = 16; o > 0; o >>= 1) q += __shfl_xor_sync(0xffffffffu, q, o);
    if ((t & 31) == 0) red[4 + (t >> 5)] = q;
    __syncthreads();
    float var = (red[4] + red[5] + red[6] + red[7]) * (1.0f/D);
    float y = d * rsqrtf(var + 1e-5f) * gamma[t] + beta[t];
    y = fmaxf(y, 0.0f);
    if (hprev) y += hprev[row*D + t];
    out[row*D + t] = y;
}

// ---------------- launcher ----------------
extern "C" void kernel_launch(void* const* d_in, const int* in_sizes, int n_in,
                              void* d_out, int out_size)
{
    const int*   x      = (const int*)d_in[0];
    const int*   ei     = (const int*)d_in[1];
    const int*   et     = (const int*)d_in[2];
    const float* emb    = (const float*)d_in[3];
    const float* w_rel  = (const float*)d_in[4];
    const float* w_root = (const float*)d_in[5];
    const float* bias   = (const float*)d_in[6];
    const float* gamma  = (const float*)d_in[7];
    const float* beta   = (const float*)d_in[8];
    float* out = (float*)d_out;
    const int* src = ei;
    const int* dst = ei + EE;

    float *hA, *hB, *Acat, *Bt;
    cudaGetSymbolAddress((void**)&hA,   g_hA);
    cudaGetSymbolAddress((void**)&hB,   g_hB);
    cudaGetSymbolAddress((void**)&Acat, g_Acat);
    cudaGetSymbolAddress((void**)&Bt,   g_Bt);

    cudaFuncSetAttribute(k_gemm_mma, cudaFuncAttributeMaxDynamicSharedMemorySize, GDSM);

    const int T = 256;
    k_zero_cnt<<<(NB+T-1)/T, T>>>();
    k_count<<<(EE+T-1)/T, T>>>(et, dst);
    k_scan1<<<SCAN_BLK, 256>>>();
    k_scan2<<<1, 512>>>();
    k_scan3<<<SCAN_BLK, 256>>>();
    k_inv<<<(NB+T-1)/T, T>>>();
    k_partition<<<(EE+T-1)/T, T>>>(src, dst, et);
    k_prep_bt<<<(LL*D*KTOT + T-1)/T, T>>>(w_rel, w_root);
    k_gather<<<(NN*32+T-1)/T, T>>>(x, emb);

    const int GB = (NN + 127) / 128;  // 391 tiles
    for (int l = 0; l < LL; l++) {
        k_agg_all<<<NN, 256>>>(hA, Acat);
        k_gemm_mma<<<GB, 256, GDSM>>>(Acat, Bt + (size_t)l*D*KTOT, bias + l*D, hB);
        float* lnout = (l == LL-1) ? out : hA;
        k_ln<<<NN, 128>>>(hB, gamma + l*D, beta + l*D, (l > 0) ? hA : nullptr, lnout);
    }
}

// round 6
// speedup vs baseline: 2.3642x; 1.2712x over previous
#include <cuda_runtime.h>
#include <math.h>
#include <stdint.h>

#define D    128
#define NN   50000
#define EE   1600000
#define RR   8
#define LL   3
#define NB   (RR*NN)
#define SCAN_BLK 391   /* ceil(NB/1024) */
#define KTOT 1152      /* 8*128 relation means + 128 root */
#define NCH  36        /* KTOT / 32 */
#define ASTRIDE 36     /* 32 + 4 pad floats */
#define STAGEB (128*ASTRIDE*4)          /* bytes per operand per stage: 18432 */
#define GDSM  (2*2*STAGEB)              /* 2 stages x (A+B) = 73728 */

// ---------------- scratch (static device arrays; no allocation) ----------------
__device__ float g_hA[NN*D];              // current h (fp32)
__device__ float g_Acat[(size_t)NN*KTOT]; // concatenated GEMM A operand (fp32)
__device__ float g_Bt[LL*D*KTOT];         // transposed weights [l][f][k] (fp32)
__device__ float g_invc[NB];
__device__ int   g_cnt[NB];
__device__ int   g_boff[NB+1];
__device__ int   g_bcur[NB];
__device__ int   g_srcs[EE];
__device__ int   g_part[512];

// ---------------- helpers ----------------
__device__ __forceinline__ uint32_t su32(const void* p) {
    uint32_t a;
    asm("{.reg .u64 t; cvta.to.shared.u64 t, %1; cvt.u32.u64 %0, t;}" : "=r"(a) : "l"(p));
    return a;
}
__device__ __forceinline__ void cp16(uint32_t s, const float* g) {
    asm volatile("cp.async.cg.shared.global [%0], [%1], 16;" :: "r"(s), "l"(g));
}
// split (v0,v1) into packed bf16x2 hi and lo parts (element k in low half, k+1 in high)
__device__ __forceinline__ void bsplit2(float v0, float v1, uint32_t& hi, uint32_t& lo) {
    asm("cvt.rn.bf16x2.f32 %0, %1, %2;" : "=r"(hi) : "f"(v1), "f"(v0));
    float h0 = __uint_as_float(hi << 16);
    float h1 = __uint_as_float(hi & 0xffff0000u);
    float l0 = v0 - h0, l1 = v1 - h1;
    asm("cvt.rn.bf16x2.f32 %0, %1, %2;" : "=r"(lo) : "f"(l1), "f"(l0));
}
__device__ __forceinline__ void mma_bf16(float* c, const uint32_t* a, const uint32_t* b) {
    asm volatile(
        "mma.sync.aligned.m16n8k16.row.col.f32.bf16.bf16.f32 "
        "{%0,%1,%2,%3},{%4,%5,%6,%7},{%8,%9},{%0,%1,%2,%3};"
        : "+f"(c[0]), "+f"(c[1]), "+f"(c[2]), "+f"(c[3])
        : "r"(a[0]), "r"(a[1]), "r"(a[2]), "r"(a[3]), "r"(b[0]), "r"(b[1]));
}

// ---------------- setup kernels ----------------
__global__ void k_zero_cnt() {
    int i = blockIdx.x*blockDim.x + threadIdx.x;
    if (i < NB) g_cnt[i] = 0;
}
__global__ void k_count(const int* __restrict__ et, const int* __restrict__ dst) {
    int e = blockIdx.x*blockDim.x + threadIdx.x;
    if (e < EE) atomicAdd(&g_cnt[et[e]*NN + dst[e]], 1);
}
__global__ void k_scan1() {
    int t = threadIdx.x;
    int base = blockIdx.x*1024 + t*4;
    int s = 0;
    #pragma unroll
    for (int j = 0; j < 4; j++) { int i = base + j; if (i < NB) s += g_cnt[i]; }
    #pragma unroll
    for (int o = 16; o > 0; o >>= 1) s += __shfl_xor_sync(0xffffffffu, s, o);
    __shared__ int ws[8];
    if ((t & 31) == 0) ws[t >> 5] = s;
    __syncthreads();
    if (t == 0) {
        int tot = 0;
        #pragma unroll
        for (int w = 0; w < 8; w++) tot += ws[w];
        g_part[blockIdx.x] = tot;
    }
}
__global__ void k_scan2() {
    __shared__ int sm[512];
    int t = threadIdx.x;
    int v = (t < SCAN_BLK) ? g_part[t] : 0;
    sm[t] = v; __syncthreads();
    for (int o = 1; o < 512; o <<= 1) {
        int y = (t >= o) ? sm[t-o] : 0;
        __syncthreads();
        sm[t] += y;
        __syncthreads();
    }
    if (t < SCAN_BLK) g_part[t] = sm[t] - v;
    if (t == 0) g_boff[NB] = EE;
}
__global__ void k_scan3() {
    int t = threadIdx.x;
    int base = blockIdx.x*1024 + t*4;
    int c[4]; int tsum = 0;
    #pragma unroll
    for (int j = 0; j < 4; j++) { int i = base + j; c[j] = (i < NB) ? g_cnt[i] : 0; tsum += c[j]; }
    int x = tsum;
    int lane = t & 31, wid = t >> 5;
    #pragma unroll
    for (int o = 1; o < 32; o <<= 1) { int y = __shfl_up_sync(0xffffffffu, x, o); if (lane >= o) x += y; }
    __shared__ int wincl[8];
    if (lane == 31) wincl[wid] = x;
    __syncthreads();
    int pre = 0;
    for (int w = 0; w < wid; w++) pre += wincl[w];
    int off = g_part[blockIdx.x] + pre + x - tsum;
    #pragma unroll
    for (int j = 0; j < 4; j++) {
        int i = base + j;
        if (i < NB) { g_boff[i] = off; g_bcur[i] = off; off += c[j]; }
    }
}
__global__ void k_inv() {
    int i = blockIdx.x*blockDim.x + threadIdx.x;
    if (i < NB) g_invc[i] = 1.0f / fmaxf((float)g_cnt[i], 1.0f);
}
__global__ void k_partition(const int* __restrict__ src, const int* __restrict__ dst,
                            const int* __restrict__ et) {
    int e = blockIdx.x*blockDim.x + threadIdx.x;
    if (e < EE) {
        int b = et[e]*NN + dst[e];
        int p = atomicAdd(&g_bcur[b], 1);
        g_srcs[p] = src[e];
    }
}
__global__ void k_gather(const int* __restrict__ x, const float* __restrict__ emb) {
    int i = blockIdx.x*blockDim.x + threadIdx.x;
    if (i < NN*32) {
        int row = i >> 5, c = i & 31;
        ((float4*)g_hA)[i] = ((const float4*)emb)[(long long)x[row]*32 + c];
    }
}

// ---------------- weight transpose: Bt[l][f][k] (fp32) ----
__global__ void k_prep_bt(const float* __restrict__ w_rel, const float* __restrict__ w_root) {
    int i = blockIdx.x*blockDim.x + threadIdx.x;
    if (i >= LL*D*KTOT) return;
    int l = i / (D*KTOT);
    int rem = i - l*D*KTOT;
    int f = rem / KTOT;
    int k = rem - f*KTOT;
    float v;
    if (k < RR*D) {
        int r = k >> 7, dd = k & 127;
        v = w_rel[(((size_t)(l*RR + r))*D + dd)*D + f];
    } else {
        int dd = k - RR*D;
        v = w_root[((size_t)l*D + dd)*D + f];
    }
    g_Bt[i] = v;
}

// ---------------- fused aggregation: 8 relation means + root copy -> A_cat ----
__global__ void k_agg_all(const float* __restrict__ h, float* __restrict__ Acat) {
    int n = blockIdx.x;
    int wid = threadIdx.x >> 5, lane = threadIdx.x & 31;
    int b = wid*NN + n;
    int beg = g_boff[b], end = g_boff[b+1];
    float4 acc = make_float4(0.f, 0.f, 0.f, 0.f);
    for (int e = beg; e < end; e++) {
        int s = g_srcs[e];
        float4 v = *(const float4*)&h[s*D + lane*4];
        acc.x += v.x; acc.y += v.y; acc.z += v.z; acc.w += v.w;
    }
    float sc = g_invc[b];
    acc.x *= sc; acc.y *= sc; acc.z *= sc; acc.w *= sc;
    *(float4*)&Acat[(size_t)n*KTOT + wid*D + lane*4] = acc;
    if (threadIdx.x < 32) {
        float4 v = *(const float4*)&h[n*D + threadIdx.x*4];
        *(float4*)&Acat[(size_t)n*KTOT + RR*D + threadIdx.x*4] = v;
    }
}

// ---------------- bf16x3 mma GEMM + fused bias/LN/ReLU/residual ----------------
// C_row = LN(A[row]@B^T + bias)*gamma+beta, relu, +hprev. 256 thr, 8 warps (2m x 4n),
// warp tile 64x32, double-buffered cp.async over 36 K=32 chunks.
__global__ void __launch_bounds__(256, 1) k_gemm_ln(
    const float* __restrict__ A, const float* __restrict__ B,
    const float* __restrict__ bias, const float* __restrict__ gamma,
    const float* __restrict__ beta, const float* __restrict__ hprev,
    float* __restrict__ dst)
{
    extern __shared__ float smf[];
    int tid = threadIdx.x, wid = tid >> 5, lane = tid & 31;
    int row0 = blockIdx.x * 128;
    int warp_m = (wid >> 2) * 64;       // 0 or 64
    int warp_n = (wid & 3) * 32;        // 0,32,64,96
    int grp = lane >> 2, qid = lane & 3;

    uint32_t sbase = su32(smf);

    float c[4][4][4];
    #pragma unroll
    for (int i = 0; i < 4; i++)
        #pragma unroll
        for (int j = 0; j < 4; j++)
            #pragma unroll
            for (int q = 0; q < 4; q++) c[i][j][q] = 0.f;

    auto load_chunk = [&](int it, int s) {
        const int kb = it * 32;
        uint32_t sA = sbase + (uint32_t)s * (2*STAGEB);
        uint32_t sB = sA + STAGEB;
        #pragma unroll
        for (int j = 0; j < 4; j++) {
            int slot = tid + j*256;           // 0..1023
            int row = slot >> 3, c16 = slot & 7;
            uint32_t off = (uint32_t)(row*ASTRIDE*4 + c16*16);
            int gm = row0 + row; if (gm >= NN) gm = NN - 1;   // clamp (never stored)
            cp16(sA + off, A + (size_t)gm*KTOT + kb + c16*4);
            cp16(sB + off, B + (size_t)row*KTOT + kb + c16*4);
        }
        asm volatile("cp.async.commit_group;" ::: "memory");
    };

    load_chunk(0, 0);
    load_chunk(1, 1);

    for (int it = 0; it < NCH; it++) {
        int s = it & 1;
        if (it < NCH-1) asm volatile("cp.async.wait_group 1;" ::: "memory");
        else            asm volatile("cp.async.wait_group 0;" ::: "memory");
        __syncthreads();
        const float* As = smf + s*(2*STAGEB/4);
        const float* Bs = As + (STAGEB/4);
        #pragma unroll
        for (int kk = 0; kk < 32; kk += 16) {
            uint32_t ah[4][4], al[4][4], bh[4][2], bl[4][2];
            #pragma unroll
            for (int i = 0; i < 4; i++) {
                int r = warp_m + i*16 + grp;
                float2 v0 = *(const float2*)&As[r*ASTRIDE + kk + 2*qid];
                float2 v1 = *(const float2*)&As[(r+8)*ASTRIDE + kk + 2*qid];
                float2 v2 = *(const float2*)&As[r*ASTRIDE + kk + 2*qid + 8];
                float2 v3 = *(const float2*)&As[(r+8)*ASTRIDE + kk + 2*qid + 8];
                bsplit2(v0.x, v0.y, ah[i][0], al[i][0]);
                bsplit2(v1.x, v1.y, ah[i][1], al[i][1]);
                bsplit2(v2.x, v2.y, ah[i][2], al[i][2]);
                bsplit2(v3.x, v3.y, ah[i][3], al[i][3]);
            }
            #pragma unroll
            for (int j = 0; j < 4; j++) {
                int nrow = warp_n + j*8 + grp;
                float2 w0 = *(const float2*)&Bs[nrow*ASTRIDE + kk + 2*qid];
                float2 w1 = *(const float2*)&Bs[nrow*ASTRIDE + kk + 2*qid + 8];
                bsplit2(w0.x, w0.y, bh[j][0], bl[j][0]);
                bsplit2(w1.x, w1.y, bh[j][1], bl[j][1]);
            }
            #pragma unroll
            for (int i = 0; i < 4; i++)
                #pragma unroll
                for (int j = 0; j < 4; j++) {
                    mma_bf16(c[i][j], al[i], bh[j]);
                    mma_bf16(c[i][j], ah[i], bl[j]);
                    mma_bf16(c[i][j], ah[i], bh[j]);
                }
        }
        __syncthreads();
        if (it + 2 < NCH) load_chunk(it + 2, s);
    }

    // ---- fused epilogue: bias + LayerNorm + ReLU + residual ----
    // smem reuse (mainloop done, all warps past final __syncthreads)
    float* redSum = smf;            // [128][4]
    float* redSq  = smf + 512;      // [128][4]
    float* s_mu   = smf + 1024;     // [128]
    float* s_rs   = smf + 1152;     // [128]
    int wn = wid & 3;

    // bias add + per-warp row partials
    float2 gset[4], bset[4];
    #pragma unroll
    for (int j = 0; j < 4; j++) {
        int col = warp_n + j*8 + qid*2;
        gset[j] = *(const float2*)&gamma[col];
        bset[j] = *(const float2*)&beta[col];
    }
    #pragma unroll
    for (int i = 0; i < 4; i++) {
        float s0 = 0.f, q0 = 0.f, s1 = 0.f, q1 = 0.f;
        #pragma unroll
        for (int j = 0; j < 4; j++) {
            int col = warp_n + j*8 + qid*2;
            float bx = bias[col], by = bias[col+1];
            c[i][j][0] += bx; c[i][j][1] += by;
            c[i][j][2] += bx; c[i][j][3] += by;
            s0 += c[i][j][0] + c[i][j][1];
            q0 += c[i][j][0]*c[i][j][0] + c[i][j][1]*c[i][j][1];
            s1 += c[i][j][2] + c[i][j][3];
            q1 += c[i][j][2]*c[i][j][2] + c[i][j][3]*c[i][j][3];
        }
        #pragma unroll
        for (int o = 1; o <= 2; o <<= 1) {
            s0 += __shfl_xor_sync(0xffffffffu, s0, o);
            q0 += __shfl_xor_sync(0xffffffffu, q0, o);
            s1 += __shfl_xor_sync(0xffffffffu, s1, o);
            q1 += __shfl_xor_sync(0xffffffffu, q1, o);
        }
        if (qid == 0) {
            int r0 = warp_m + i*16 + grp;
            redSum[r0*4 + wn] = s0;  redSq[r0*4 + wn] = q0;
            redSum[(r0+8)*4 + wn] = s1;  redSq[(r0+8)*4 + wn] = q1;
        }
    }
    __syncthreads();
    if (tid < 128) {
        float s = redSum[tid*4+0] + redSum[tid*4+1] + redSum[tid*4+2] + redSum[tid*4+3];
        float q = redSq[tid*4+0] + redSq[tid*4+1] + redSq[tid*4+2] + redSq[tid*4+3];
        float mu = s * (1.0f/D);
        float var = q * (1.0f/D) - mu*mu;
        s_mu[tid] = mu;
        s_rs[tid] = rsqrtf(var + 1e-5f);
    }
    __syncthreads();

    #pragma unroll
    for (int i = 0; i < 4; i++) {
        int lr0 = warp_m + i*16 + grp;
        int lr1 = lr0 + 8;
        float mu0 = s_mu[lr0], rs0 = s_rs[lr0];
        float mu1 = s_mu[lr1], rs1 = s_rs[lr1];
        int gm0 = row0 + lr0, gm1 = row0 + lr1;
        #pragma unroll
        for (int j = 0; j < 4; j++) {
            int col = warp_n + j*8 + qid*2;
            if (gm0 < NN) {
                float y0 = fmaxf((c[i][j][0]-mu0)*rs0*gset[j].x + bset[j].x, 0.f);
                float y1 = fmaxf((c[i][j][1]-mu0)*rs0*gset[j].y + bset[j].y, 0.f);
                if (hprev) {
                    const float2 p = *(const float2*)&hprev[(size_t)gm0*D + col];
                    y0 += p.x; y1 += p.y;
                }
                *(float2*)&dst[(size_t)gm0*D + col] = make_float2(y0, y1);
            }
            if (gm1 < NN) {
                float y0 = fmaxf((c[i][j][2]-mu1)*rs1*gset[j].x + bset[j].x, 0.f);
                float y1 = fmaxf((c[i][j][3]-mu1)*rs1*gset[j].y + bset[j].y, 0.f);
                if (hprev) {
                    const float2 p = *(const float2*)&hprev[(size_t)gm1*D + col];
                    y0 += p.x; y1 += p.y;
                }
                *(float2*)&dst[(size_t)gm1*D + col] = make_float2(y0, y1);
            }
        }
    }
}

// ---------------- launcher ----------------
extern "C" void kernel_launch(void* const* d_in, const int* in_sizes, int n_in,
                              void* d_out, int out_size)
{
    const int*   x      = (const int*)d_in[0];
    const int*   ei     = (const int*)d_in[1];
    const int*   et     = (const int*)d_in[2];
    const float* emb    = (const float*)d_in[3];
    const float* w_rel  = (const float*)d_in[4];
    const float* w_root = (const float*)d_in[5];
    const float* bias   = (const float*)d_in[6];
    const float* gamma  = (const float*)d_in[7];
    const float* beta   = (const float*)d_in[8];
    float* out = (float*)d_out;
    const int* src = ei;
    const int* dst = ei + EE;

    float *hA, *Acat, *Bt;
    cudaGetSymbolAddress((void**)&hA,   g_hA);
    cudaGetSymbolAddress((void**)&Acat, g_Acat);
    cudaGetSymbolAddress((void**)&Bt,   g_Bt);

    cudaFuncSetAttribute(k_gemm_ln, cudaFuncAttributeMaxDynamicSharedMemorySize, GDSM);

    const int T = 256;
    k_zero_cnt<<<(NB+T-1)/T, T>>>();
    k_count<<<(EE+T-1)/T, T>>>(et, dst);
    k_scan1<<<SCAN_BLK, 256>>>();
    k_scan2<<<1, 512>>>();
    k_scan3<<<SCAN_BLK, 256>>>();
    k_inv<<<(NB+T-1)/T, T>>>();
    k_partition<<<(EE+T-1)/T, T>>>(src, dst, et);
    k_prep_bt<<<(LL*D*KTOT + T-1)/T, T>>>(w_rel, w_root);
    k_gather<<<(NN*32+T-1)/T, T>>>(x, emb);

    const int GB = (NN + 127) / 128;  // 391 tiles
    for (int l = 0; l < LL; l++) {
        k_agg_all<<<NN, 256>>>(hA, Acat);
        k_gemm_ln<<<GB, 256, GDSM>>>(Acat, Bt + (size_t)l*D*KTOT, bias + l*D,
                                     gamma + l*D, beta + l*D,
                                     (l > 0) ? hA : nullptr,
                                     (l == LL-1) ? out : hA);
    }
}